// round 3
// baseline (speedup 1.0000x reference)
#include <cuda_runtime.h>
#include <stdint.h>

// Instant-NGP hash-grid encode + fused MLP 32->64->64->3, fp32.
// R2 change: weights/biases moved from shared memory to __constant__ memory.
// All weight operands are warp-uniform with immediate offsets -> LDCU on the
// uniform-const port, freeing the L1tex crossbar for the hash-table gathers.

#define HASHMAP_SIZE (1u << 17)
#define N_LEVELS 16

__device__ __constant__ float SCALES[16] = {
    16.0f, 24.0f, 36.0f, 54.0f, 81.0f, 121.5f, 182.25f, 273.375f,
    410.0625f, 615.09375f, 922.640625f, 1383.9609375f,
    2075.94140625f, 3113.912109375f, 4670.8681640625f, 7006.30224609375f
};

// MLP weights in the constant bank (25.1 KB total, fits 64 KB).
__device__ __constant__ float cw0[32 * 64];
__device__ __constant__ float cb0[64];
__device__ __constant__ float cw1[64 * 64];
__device__ __constant__ float cb1[64];
__device__ __constant__ float cw2[64 * 3];
__device__ __constant__ float cb2[3];

// Packed dual-fp32 FMA (sm_100+). ptxas never auto-emits this from C++.
__device__ __forceinline__ float2 ffma2(float2 a, float2 b, float2 c) {
    float2 d;
    asm("{\n\t"
        ".reg .b64 ra, rb, rc, rd;\n\t"
        "mov.b64 ra, {%2, %3};\n\t"
        "mov.b64 rb, {%4, %5};\n\t"
        "mov.b64 rc, {%6, %7};\n\t"
        "fma.rn.f32x2 rd, ra, rb, rc;\n\t"
        "mov.b64 {%0, %1}, rd;\n\t"
        "}"
        : "=f"(d.x), "=f"(d.y)
        : "f"(a.x), "f"(a.y), "f"(b.x), "f"(b.y), "f"(c.x), "f"(c.y));
    return d;
}

__global__ void __launch_bounds__(128)
fused_mlp_kernel(const float2* __restrict__ x,
                 const float*  __restrict__ enc,
                 float* __restrict__ out, int N)
{
    const int gi = blockIdx.x * 128 + threadIdx.x;
    if (gi >= N) return;

    const float2 xi = x[gi];

    // ---------------- Hash-grid encode: 16 levels x 2 features ----------------
    float feat[32];
    #pragma unroll
    for (int l = 0; l < N_LEVELS; l++) {
        const float s  = SCALES[l];
        const float px = xi.x * s;
        const float py = xi.y * s;
        const float fx = floorf(px);
        const float fy = floorf(py);
        const float tx = px - fx;
        const float ty = py - fy;
        const unsigned ix0 = (unsigned)fx;
        const unsigned iy0 = (unsigned)fy;

        float accx = 0.0f, accy = 0.0f;
        #pragma unroll
        for (int c = 0; c < 4; c++) {
            const unsigned cx = (unsigned)(c >> 1);
            const unsigned cy = (unsigned)(c & 1);
            const unsigned h   = (ix0 + cx) ^ ((iy0 + cy) * 2654435761u);
            const unsigned idx = h & (HASHMAP_SIZE - 1u);
            const float2 e = __ldg((const float2*)(enc + ((idx * 16u + (unsigned)l) * 2u)));
            const float wx = cx ? tx : (1.0f - tx);
            const float wy = cy ? ty : (1.0f - ty);
            const float w  = wx * wy;
            accx = fmaf(w, e.x, accx);
            accy = fmaf(w, e.y, accy);
        }
        feat[2 * l + 0] = accx;
        feat[2 * l + 1] = accy;
    }

    // ---------------- Layer 1: [32] -> relu[64], packed f32x2 ----------------
    float2 h0[32];
    #pragma unroll
    for (int j = 0; j < 32; j++)
        h0[j] = make_float2(cb0[2 * j], cb0[2 * j + 1]);
    #pragma unroll
    for (int k = 0; k < 32; k++) {
        const float2 a = make_float2(feat[k], feat[k]);
        #pragma unroll
        for (int j = 0; j < 32; j++)
            h0[j] = ffma2(a, make_float2(cw0[k * 64 + 2 * j], cw0[k * 64 + 2 * j + 1]), h0[j]);
    }
    #pragma unroll
    for (int j = 0; j < 32; j++) {
        h0[j].x = fmaxf(h0[j].x, 0.0f);
        h0[j].y = fmaxf(h0[j].y, 0.0f);
    }

    // ------- Layer 2 (two 32-wide halves) + fused Layer 3 accumulate -------
    float o0 = cb2[0], o1 = cb2[1], o2 = cb2[2];
    #pragma unroll
    for (int half = 0; half < 2; half++) {
        float2 h1[16];
        #pragma unroll
        for (int j = 0; j < 16; j++)
            h1[j] = make_float2(cb1[32 * half + 2 * j], cb1[32 * half + 2 * j + 1]);
        #pragma unroll
        for (int k = 0; k < 64; k++) {
            const float a = (k & 1) ? h0[k >> 1].y : h0[k >> 1].x;
            const float2 av = make_float2(a, a);
            #pragma unroll
            for (int j = 0; j < 16; j++)
                h1[j] = ffma2(av,
                              make_float2(cw1[k * 64 + 32 * half + 2 * j],
                                          cw1[k * 64 + 32 * half + 2 * j + 1]),
                              h1[j]);
        }
        #pragma unroll
        for (int j = 0; j < 16; j++) {
            const float v0 = fmaxf(h1[j].x, 0.0f);
            const float v1 = fmaxf(h1[j].y, 0.0f);
            const int r0 = 32 * half + 2 * j;
            const int r1 = r0 + 1;
            o0 = fmaf(v0, cw2[r0 * 3 + 0], o0);
            o1 = fmaf(v0, cw2[r0 * 3 + 1], o1);
            o2 = fmaf(v0, cw2[r0 * 3 + 2], o2);
            o0 = fmaf(v1, cw2[r1 * 3 + 0], o0);
            o1 = fmaf(v1, cw2[r1 * 3 + 1], o1);
            o2 = fmaf(v1, cw2[r1 * 3 + 2], o2);
        }
    }

    out[gi * 3 + 0] = o0;
    out[gi * 3 + 1] = o1;
    out[gi * 3 + 2] = o2;
}

extern "C" void kernel_launch(void* const* d_in, const int* in_sizes, int n_in,
                              void* d_out, int out_size)
{
    const float2* x   = (const float2*)d_in[0];
    const float*  enc = (const float*) d_in[1];
    float* out = (float*)d_out;

    // Stage weights into the constant bank (device-to-device async memcpys:
    // graph-capturable, allocation-free).
    cudaMemcpyToSymbolAsync(cw0, d_in[2], 32 * 64 * sizeof(float), 0, cudaMemcpyDeviceToDevice, 0);
    cudaMemcpyToSymbolAsync(cb0, d_in[3], 64 * sizeof(float),      0, cudaMemcpyDeviceToDevice, 0);
    cudaMemcpyToSymbolAsync(cw1, d_in[4], 64 * 64 * sizeof(float), 0, cudaMemcpyDeviceToDevice, 0);
    cudaMemcpyToSymbolAsync(cb1, d_in[5], 64 * sizeof(float),      0, cudaMemcpyDeviceToDevice, 0);
    cudaMemcpyToSymbolAsync(cw2, d_in[6], 64 * 3 * sizeof(float),  0, cudaMemcpyDeviceToDevice, 0);
    cudaMemcpyToSymbolAsync(cb2, d_in[7], 3 * sizeof(float),       0, cudaMemcpyDeviceToDevice, 0);

    const int N = in_sizes[0] / 2;
    const int threads = 128;
    const int blocks = (N + threads - 1) / threads;
    fused_mlp_kernel<<<blocks, threads>>>(x, enc, out, N);
}

// round 4
// speedup vs baseline: 1.3283x; 1.3283x over previous
#include <cuda_runtime.h>
#include <stdint.h>

// Instant-NGP hash-grid encode + fused MLP 32->64->64->3, fp32.
// R3: weights back in shared (R2's constant port was half-rate LDC), but all
// weight broadcasts widened to LDS.128 (float4) -> halves L1tex wavefronts.

#define HASHMAP_SIZE (1u << 17)
#define N_LEVELS 16

__device__ __constant__ float SCALES[16] = {
    16.0f, 24.0f, 36.0f, 54.0f, 81.0f, 121.5f, 182.25f, 273.375f,
    410.0625f, 615.09375f, 922.640625f, 1383.9609375f,
    2075.94140625f, 3113.912109375f, 4670.8681640625f, 7006.30224609375f
};

// Packed dual-fp32 FMA (sm_100+). ptxas never auto-emits this from C++.
__device__ __forceinline__ float2 ffma2(float2 a, float2 b, float2 c) {
    float2 d;
    asm("{\n\t"
        ".reg .b64 ra, rb, rc, rd;\n\t"
        "mov.b64 ra, {%2, %3};\n\t"
        "mov.b64 rb, {%4, %5};\n\t"
        "mov.b64 rc, {%6, %7};\n\t"
        "fma.rn.f32x2 rd, ra, rb, rc;\n\t"
        "mov.b64 {%0, %1}, rd;\n\t"
        "}"
        : "=f"(d.x), "=f"(d.y)
        : "f"(a.x), "f"(a.y), "f"(b.x), "f"(b.y), "f"(c.x), "f"(c.y));
    return d;
}

__global__ void __launch_bounds__(128)
fused_mlp_kernel(const float2* __restrict__ x,
                 const float*  __restrict__ enc,
                 const float*  __restrict__ w0, const float* __restrict__ b0,
                 const float*  __restrict__ w1, const float* __restrict__ b1,
                 const float*  __restrict__ w2, const float* __restrict__ b2,
                 float* __restrict__ out, int N)
{
    // Weights in shared, laid out for float4 (LDS.128) broadcast reads.
    __shared__ float4 sw0[32 * 16];   // w0 [32,64]: row k -> 16 float4
    __shared__ float4 sw1[64 * 16];   // w1 [64,64]: row k -> 16 float4
    __shared__ float4 sw2[64];        // w2 [64,3] padded: row r -> (w,w,w,0)
    __shared__ float2 sb0[32], sb1[32];
    __shared__ float  sb2[4];

    const int tid = threadIdx.x;
    for (int i = tid; i < 32 * 16; i += 128) sw0[i] = ((const float4*)w0)[i];
    for (int i = tid; i < 64 * 16; i += 128) sw1[i] = ((const float4*)w1)[i];
    if (tid < 64) {
        sw2[tid] = make_float4(w2[tid * 3 + 0], w2[tid * 3 + 1], w2[tid * 3 + 2], 0.0f);
    }
    if (tid < 32) {
        sb0[tid] = ((const float2*)b0)[tid];
        sb1[tid] = ((const float2*)b1)[tid];
    }
    if (tid < 3) sb2[tid] = b2[tid];
    __syncthreads();

    const int gi = blockIdx.x * 128 + tid;
    if (gi >= N) return;

    const float2 xi = x[gi];

    // ---------------- Hash-grid encode: 16 levels x 2 features ----------------
    float feat[32];
    #pragma unroll
    for (int l = 0; l < N_LEVELS; l++) {
        const float s  = SCALES[l];
        const float px = xi.x * s;
        const float py = xi.y * s;
        const float fx = floorf(px);
        const float fy = floorf(py);
        const float tx = px - fx;
        const float ty = py - fy;
        const unsigned ix0 = (unsigned)fx;
        const unsigned iy0 = (unsigned)fy;

        float accx = 0.0f, accy = 0.0f;
        #pragma unroll
        for (int c = 0; c < 4; c++) {
            const unsigned cx = (unsigned)(c >> 1);
            const unsigned cy = (unsigned)(c & 1);
            const unsigned h   = (ix0 + cx) ^ ((iy0 + cy) * 2654435761u);
            const unsigned idx = h & (HASHMAP_SIZE - 1u);
            const float2 e = __ldg((const float2*)(enc + ((idx * 16u + (unsigned)l) * 2u)));
            const float wx = cx ? tx : (1.0f - tx);
            const float wy = cy ? ty : (1.0f - ty);
            const float w  = wx * wy;
            accx = fmaf(w, e.x, accx);
            accy = fmaf(w, e.y, accy);
        }
        feat[2 * l + 0] = accx;
        feat[2 * l + 1] = accy;
    }

    // ---------------- Layer 1: [32] -> relu[64], packed f32x2 ----------------
    float2 h0[32];
    #pragma unroll
    for (int j = 0; j < 32; j++)
        h0[j] = sb0[j];
    #pragma unroll
    for (int k = 0; k < 32; k++) {
        const float2 a = make_float2(feat[k], feat[k]);
        #pragma unroll
        for (int j4 = 0; j4 < 16; j4++) {
            const float4 w = sw0[k * 16 + j4];
            h0[2 * j4 + 0] = ffma2(a, make_float2(w.x, w.y), h0[2 * j4 + 0]);
            h0[2 * j4 + 1] = ffma2(a, make_float2(w.z, w.w), h0[2 * j4 + 1]);
        }
    }
    #pragma unroll
    for (int j = 0; j < 32; j++) {
        h0[j].x = fmaxf(h0[j].x, 0.0f);
        h0[j].y = fmaxf(h0[j].y, 0.0f);
    }

    // ------- Layer 2 (two 32-wide halves) + fused Layer 3 accumulate -------
    float o0 = sb2[0], o1 = sb2[1], o2 = sb2[2];
    #pragma unroll
    for (int half = 0; half < 2; half++) {
        float2 h1[16];
        #pragma unroll
        for (int j = 0; j < 16; j++)
            h1[j] = sb1[16 * half + j];
        #pragma unroll
        for (int k = 0; k < 64; k++) {
            const float a = (k & 1) ? h0[k >> 1].y : h0[k >> 1].x;
            const float2 av = make_float2(a, a);
            #pragma unroll
            for (int j4 = 0; j4 < 8; j4++) {
                const float4 w = sw1[k * 16 + 8 * half + j4];
                h1[2 * j4 + 0] = ffma2(av, make_float2(w.x, w.y), h1[2 * j4 + 0]);
                h1[2 * j4 + 1] = ffma2(av, make_float2(w.z, w.w), h1[2 * j4 + 1]);
            }
        }
        #pragma unroll
        for (int j = 0; j < 16; j++) {
            const float v0 = fmaxf(h1[j].x, 0.0f);
            const float v1 = fmaxf(h1[j].y, 0.0f);
            const int r0 = 32 * half + 2 * j;
            const float4 wr0 = sw2[r0];
            const float4 wr1 = sw2[r0 + 1];
            o0 = fmaf(v0, wr0.x, o0);
            o1 = fmaf(v0, wr0.y, o1);
            o2 = fmaf(v0, wr0.z, o2);
            o0 = fmaf(v1, wr1.x, o0);
            o1 = fmaf(v1, wr1.y, o1);
            o2 = fmaf(v1, wr1.z, o2);
        }
    }

    out[gi * 3 + 0] = o0;
    out[gi * 3 + 1] = o1;
    out[gi * 3 + 2] = o2;
}

extern "C" void kernel_launch(void* const* d_in, const int* in_sizes, int n_in,
                              void* d_out, int out_size)
{
    const float2* x   = (const float2*)d_in[0];
    const float*  enc = (const float*) d_in[1];
    const float*  w0  = (const float*) d_in[2];
    const float*  b0  = (const float*) d_in[3];
    const float*  w1  = (const float*) d_in[4];
    const float*  b1  = (const float*) d_in[5];
    const float*  w2  = (const float*) d_in[6];
    const float*  b2  = (const float*) d_in[7];
    float* out = (float*)d_out;

    const int N = in_sizes[0] / 2;
    const int threads = 128;
    const int blocks = (N + threads - 1) / threads;
    fused_mlp_kernel<<<blocks, threads>>>(x, enc, w0, b0, w1, b1, w2, b2, out, N);
}

// round 6
// speedup vs baseline: 2.3705x; 1.7847x over previous
#include <cuda_runtime.h>
#include <cuda_fp16.h>
#include <stdint.h>

// Instant-NGP hash encode + MLP 32->64->64->3.
// R5: MLP layers 1+2 on portable HMMA (mma.sync m16n8k16 f16->f32), ldmatrix-fed.
// Weights fp16 in smem (144B row stride, conflict-free), activations round-trip
// through a per-warp smem tile. Layer 3 scalar fp32 + 4-lane shuffle reduce.

#define HASHMAP_SIZE (1u << 17)

__device__ __constant__ float SCALES[16] = {
    16.0f, 24.0f, 36.0f, 54.0f, 81.0f, 121.5f, 182.25f, 273.375f,
    410.0625f, 615.09375f, 922.640625f, 1383.9609375f,
    2075.94140625f, 3113.912109375f, 4670.8681640625f, 7006.30224609375f
};

// ---- smem layout (byte offsets), all rows 144B stride (9 x 16B banks) ----
#define STRIDE   144
#define W0_OFF   0                    // 32 rows (K) x 64 halves (N)
#define W1_OFF   4608                 // 64 rows (K) x 64 halves (N)
#define W2_OFF   13824                // 64 x float4 (w2 row padded)
#define B0_OFF   14848                // 64 floats
#define B1_OFF   15104                // 64 floats
#define ACT_OFF  15360                // 4 warps x 32 rows x 144B
#define SMEM_TOTAL 33792

__device__ __forceinline__ uint32_t smem_u32(const void* p) {
    uint32_t a;
    asm("{ .reg .u64 t; cvta.to.shared.u64 t, %1; cvt.u32.u64 %0, t; }"
        : "=r"(a) : "l"(p));
    return a;
}

#define LDM_X4(r0, r1, r2, r3, addr) \
    asm volatile("ldmatrix.sync.aligned.m8n8.x4.shared.b16 {%0,%1,%2,%3}, [%4];" \
        : "=r"(r0), "=r"(r1), "=r"(r2), "=r"(r3) : "r"(addr))

#define LDM_X4_T(r0, r1, r2, r3, addr) \
    asm volatile("ldmatrix.sync.aligned.m8n8.x4.trans.shared.b16 {%0,%1,%2,%3}, [%4];" \
        : "=r"(r0), "=r"(r1), "=r"(r2), "=r"(r3) : "r"(addr))

#define MMA16816(d, a0, a1, a2, a3, b0, b1) \
    asm volatile("mma.sync.aligned.m16n8k16.row.col.f32.f16.f16.f32 " \
        "{%0,%1,%2,%3}, {%4,%5,%6,%7}, {%8,%9}, {%0,%1,%2,%3};" \
        : "+f"((d)[0]), "+f"((d)[1]), "+f"((d)[2]), "+f"((d)[3]) \
        : "r"(a0), "r"(a1), "r"(a2), "r"(a3), "r"(b0), "r"(b1))

__global__ void __launch_bounds__(128)
fused_mlp_kernel(const float2* __restrict__ x,
                 const float*  __restrict__ enc,
                 const float*  __restrict__ w0, const float* __restrict__ b0,
                 const float*  __restrict__ w1, const float* __restrict__ b1,
                 const float*  __restrict__ w2, const float* __restrict__ b2,
                 float* __restrict__ out, int N)
{
    __shared__ __align__(16) uint8_t sm[SMEM_TOTAL];
    const uint32_t sbase = smem_u32(sm);

    const int tid  = threadIdx.x;
    const int wrp  = tid >> 5;
    const int lane = tid & 31;
    const int gi   = blockIdx.x * 128 + tid;

    // ---- Stage weights fp32->fp16 into smem (144B stride rows) ----
    for (int i = tid; i < 1024; i += 128) {            // w0: [32 K][64 N]
        const int k = i >> 5, n2 = i & 31;
        const float2 v = ((const float2*)w0)[i];
        *(__half2*)(sm + W0_OFF + k * STRIDE + n2 * 4) = __floats2half2_rn(v.x, v.y);
    }
    for (int i = tid; i < 2048; i += 128) {            // w1: [64 K][64 N]
        const int k = i >> 5, n2 = i & 31;
        const float2 v = ((const float2*)w1)[i];
        *(__half2*)(sm + W1_OFF + k * STRIDE + n2 * 4) = __floats2half2_rn(v.x, v.y);
    }
    if (tid < 64) {
        ((float4*)(sm + W2_OFF))[tid] =
            make_float4(w2[tid * 3 + 0], w2[tid * 3 + 1], w2[tid * 3 + 2], 0.0f);
        ((float*)(sm + B0_OFF))[tid] = b0[tid];
        ((float*)(sm + B1_OFF))[tid] = b1[tid];
    }

    // ---------------- Hash-grid encode (exact fp32 math) ----------------
    const float2 xi = (gi < N) ? x[gi] : make_float2(0.0f, 0.0f);
    float feat[32];
    #pragma unroll
    for (int l = 0; l < 16; l++) {
        const float s  = SCALES[l];
        const float px = xi.x * s, py = xi.y * s;
        const float fx = floorf(px), fy = floorf(py);
        const float tx = px - fx,  ty = py - fy;
        const unsigned ix0 = (unsigned)fx, iy0 = (unsigned)fy;
        float accx = 0.0f, accy = 0.0f;
        #pragma unroll
        for (int c = 0; c < 4; c++) {
            const unsigned cx = (unsigned)(c >> 1);
            const unsigned cy = (unsigned)(c & 1);
            const unsigned h   = (ix0 + cx) ^ ((iy0 + cy) * 2654435761u);
            const unsigned idx = h & (HASHMAP_SIZE - 1u);
            const float2 e = __ldg((const float2*)(enc + ((idx * 16u + (unsigned)l) * 2u)));
            const float wx = cx ? tx : (1.0f - tx);
            const float wy = cy ? ty : (1.0f - ty);
            const float w  = wx * wy;
            accx = fmaf(w, e.x, accx);
            accy = fmaf(w, e.y, accy);
        }
        feat[2 * l + 0] = accx;
        feat[2 * l + 1] = accy;
    }

    // Store feats (fp16) to this warp's act tile: row=lane, 64B of data
    const uint32_t actBase = sbase + ACT_OFF + wrp * 32 * STRIDE;
    {
        uint32_t fp[16];
        #pragma unroll
        for (int p = 0; p < 16; p++) {
            const __half2 h2 = __floats2half2_rn(feat[2 * p], feat[2 * p + 1]);
            fp[p] = *(const uint32_t*)&h2;
        }
        uint8_t* row = sm + ACT_OFF + (wrp * 32 + lane) * STRIDE;
        #pragma unroll
        for (int c = 0; c < 4; c++)
            *(uint4*)(row + c * 16) =
                make_uint4(fp[4 * c], fp[4 * c + 1], fp[4 * c + 2], fp[4 * c + 3]);
    }
    __syncthreads();   // weights + feats visible

    // Fragment address helpers
    const uint32_t aRow   = (uint32_t)(lane & 15);
    const uint32_t aColB  = (uint32_t)((lane >> 4) << 4);
    const int      bGrp   = lane >> 3;
    const uint32_t bRow   = (uint32_t)((lane & 7) + ((bGrp & 1) << 3));
    const uint32_t bColB  = (uint32_t)((bGrp >> 1) << 4);

    float acc[2][8][4];

    // ---------------- Layer 1: [32x32] @ [32x64] ----------------
    #pragma unroll
    for (int mt = 0; mt < 2; mt++)
        #pragma unroll
        for (int nt = 0; nt < 8; nt++)
            #pragma unroll
            for (int q = 0; q < 4; q++) acc[mt][nt][q] = 0.0f;

    #pragma unroll
    for (int kt = 0; kt < 2; kt++) {
        uint32_t a0[4], a1[4];
        LDM_X4(a0[0], a0[1], a0[2], a0[3],
               actBase + (0 * 16 + aRow) * STRIDE + aColB + kt * 32);
        LDM_X4(a1[0], a1[1], a1[2], a1[3],
               actBase + (1 * 16 + aRow) * STRIDE + aColB + kt * 32);
        #pragma unroll
        for (int ntp = 0; ntp < 4; ntp++) {
            uint32_t bf[4];
            LDM_X4_T(bf[0], bf[1], bf[2], bf[3],
                     sbase + W0_OFF + (kt * 16 + bRow) * STRIDE + ntp * 32 + bColB);
            MMA16816(acc[0][2 * ntp + 0], a0[0], a0[1], a0[2], a0[3], bf[0], bf[1]);
            MMA16816(acc[0][2 * ntp + 1], a0[0], a0[1], a0[2], a0[3], bf[2], bf[3]);
            MMA16816(acc[1][2 * ntp + 0], a1[0], a1[1], a1[2], a1[3], bf[0], bf[1]);
            MMA16816(acc[1][2 * ntp + 1], a1[0], a1[1], a1[2], a1[3], bf[2], bf[3]);
        }
    }

    // Epilogue 1: relu(acc + b0) -> fp16 -> act tile (overwrites feats)
    __syncwarp();
    {
        const float* bb0 = (const float*)(sm + B0_OFF);
        const int g = lane >> 2, cp = (lane & 3) * 2;
        #pragma unroll
        for (int mt = 0; mt < 2; mt++)
            #pragma unroll
            for (int nt = 0; nt < 8; nt++) {
                const int col = nt * 8 + cp;
                const float bA = bb0[col], bB = bb0[col + 1];
                const __half2 hA = __floats2half2_rn(
                    fmaxf(acc[mt][nt][0] + bA, 0.0f), fmaxf(acc[mt][nt][1] + bB, 0.0f));
                const __half2 hB = __floats2half2_rn(
                    fmaxf(acc[mt][nt][2] + bA, 0.0f), fmaxf(acc[mt][nt][3] + bB, 0.0f));
                uint8_t* base = sm + ACT_OFF + wrp * 32 * STRIDE;
                *(uint32_t*)(base + (mt * 16 + g)     * STRIDE + col * 2) = *(const uint32_t*)&hA;
                *(uint32_t*)(base + (mt * 16 + g + 8) * STRIDE + col * 2) = *(const uint32_t*)&hB;
            }
    }
    __syncwarp();

    // ---------------- Layer 2: [32x64] @ [64x64] ----------------
    #pragma unroll
    for (int mt = 0; mt < 2; mt++)
        #pragma unroll
        for (int nt = 0; nt < 8; nt++)
            #pragma unroll
            for (int q = 0; q < 4; q++) acc[mt][nt][q] = 0.0f;

    #pragma unroll
    for (int kt = 0; kt < 4; kt++) {
        uint32_t a0[4], a1[4];
        LDM_X4(a0[0], a0[1], a0[2], a0[3],
               actBase + (0 * 16 + aRow) * STRIDE + aColB + kt * 32);
        LDM_X4(a1[0], a1[1], a1[2], a1[3],
               actBase + (1 * 16 + aRow) * STRIDE + aColB + kt * 32);
        #pragma unroll
        for (int ntp = 0; ntp < 4; ntp++) {
            uint32_t bf[4];
            LDM_X4_T(bf[0], bf[1], bf[2], bf[3],
                     sbase + W1_OFF + (kt * 16 + bRow) * STRIDE + ntp * 32 + bColB);
            MMA16816(acc[0][2 * ntp + 0], a0[0], a0[1], a0[2], a0[3], bf[0], bf[1]);
            MMA16816(acc[0][2 * ntp + 1], a0[0], a0[1], a0[2], a0[3], bf[2], bf[3]);
            MMA16816(acc[1][2 * ntp + 0], a1[0], a1[1], a1[2], a1[3], bf[0], bf[1]);
            MMA16816(acc[1][2 * ntp + 1], a1[0], a1[1], a1[2], a1[3], bf[2], bf[3]);
        }
    }

    // Epilogue 2: relu(acc + b1), layer 3 fp32, 4-lane shuffle reduce, store
    {
        const float*  bb1 = (const float*)(sm + B1_OFF);
        const float4* ww2 = (const float4*)(sm + W2_OFF);
        const int g = lane >> 2, cp = (lane & 3) * 2;
        #pragma unroll
        for (int mt = 0; mt < 2; mt++) {
            float oA0 = 0.0f, oA1 = 0.0f, oA2 = 0.0f;   // row mt*16+g
            float oB0 = 0.0f, oB1 = 0.0f, oB2 = 0.0f;   // row mt*16+g+8
            #pragma unroll
            for (int nt = 0; nt < 8; nt++) {
                const int col = nt * 8 + cp;
                const float4 wA = ww2[col];
                const float4 wB = ww2[col + 1];
                const float bA = bb1[col], bB = bb1[col + 1];
                const float vA0 = fmaxf(acc[mt][nt][0] + bA, 0.0f);
                const float vA1 = fmaxf(acc[mt][nt][1] + bB, 0.0f);
                const float vB0 = fmaxf(acc[mt][nt][2] + bA, 0.0f);
                const float vB1 = fmaxf(acc[mt][nt][3] + bB, 0.0f);
                oA0 = fmaf(vA0, wA.x, fmaf(vA1, wB.x, oA0));
                oA1 = fmaf(vA0, wA.y, fmaf(vA1, wB.y, oA1));
                oA2 = fmaf(vA0, wA.z, fmaf(vA1, wB.z, oA2));
                oB0 = fmaf(vB0, wA.x, fmaf(vB1, wB.x, oB0));
                oB1 = fmaf(vB0, wA.y, fmaf(vB1, wB.y, oB1));
                oB2 = fmaf(vB0, wA.z, fmaf(vB1, wB.z, oB2));
            }
            #pragma unroll
            for (int d = 1; d < 4; d <<= 1) {
                oA0 += __shfl_xor_sync(0xffffffffu, oA0, d);
                oA1 += __shfl_xor_sync(0xffffffffu, oA1, d);
                oA2 += __shfl_xor_sync(0xffffffffu, oA2, d);
                oB0 += __shfl_xor_sync(0xffffffffu, oB0, d);
                oB1 += __shfl_xor_sync(0xffffffffu, oB1, d);
                oB2 += __shfl_xor_sync(0xffffffffu, oB2, d);
            }
            if ((lane & 3) == 0) {
                const float c0 = __ldg(b2 + 0), c1 = __ldg(b2 + 1), c2 = __ldg(b2 + 2);
                const int pA = blockIdx.x * 128 + wrp * 32 + mt * 16 + g;
                const int pB = pA + 8;
                if (pA < N) {
                    out[pA * 3 + 0] = oA0 + c0;
                    out[pA * 3 + 1] = oA1 + c1;
                    out[pA * 3 + 2] = oA2 + c2;
                }
                if (pB < N) {
                    out[pB * 3 + 0] = oB0 + c0;
                    out[pB * 3 + 1] = oB1 + c1;
                    out[pB * 3 + 2] = oB2 + c2;
                }
            }
        }
    }
}

extern "C" void kernel_launch(void* const* d_in, const int* in_sizes, int n_in,
                              void* d_out, int out_size)
{
    const float2* x   = (const float2*)d_in[0];
    const float*  enc = (const float*) d_in[1];
    const float*  w0  = (const float*) d_in[2];
    const float*  b0  = (const float*) d_in[3];
    const float*  w1  = (const float*) d_in[4];
    const float*  b1  = (const float*) d_in[5];
    const float*  w2  = (const float*) d_in[6];
    const float*  b2  = (const float*) d_in[7];
    float* out = (float*)d_out;

    const int N = in_sizes[0] / 2;
    const int blocks = (N + 127) / 128;
    fused_mlp_kernel<<<blocks, 128>>>(x, enc, w0, b0, w1, b1, w2, b2, out, N);
}

// round 7
// speedup vs baseline: 3.1278x; 1.3194x over previous
#include <cuda_runtime.h>
#include <cuda_fp16.h>
#include <stdint.h>

// Instant-NGP hash encode + MLP 32->64->64->3.
// R6: encoding table relayout [idx][level][feat] -> [level][idx][feat] so the
// two x-corner entries (i1 == i0^1 when ix even) share one 16B block; gather
// becomes one LDG.128 + predicated LDG.64 per (level, y-corner). MLP unchanged
// (HMMA m16n8k16 from R5).

#define HASHMAP_SIZE (1u << 17)
#define HMASK (HASHMAP_SIZE - 1u)

__device__ __constant__ float SCALES[16] = {
    16.0f, 24.0f, 36.0f, 54.0f, 81.0f, 121.5f, 182.25f, 273.375f,
    410.0625f, 615.09375f, 922.640625f, 1383.9609375f,
    2075.94140625f, 3113.912109375f, 4670.8681640625f, 7006.30224609375f
};

// Relayouted table: [level][idx][2 floats] = 16 MB
__device__ __align__(16) float g_enc2[16 * HASHMAP_SIZE * 2];

__global__ void __launch_bounds__(256)
relayout_kernel(const float* __restrict__ enc)
{
    const unsigned j = blockIdx.x * 256 + threadIdx.x;   // 0 .. 16*2^17-1
    const unsigned l   = j >> 17;
    const unsigned idx = j & HMASK;
    ((float2*)g_enc2)[j] = ((const float2*)enc)[idx * 16 + l];
}

// ---- smem layout (byte offsets), all rows 144B stride (9 x 16B banks) ----
#define STRIDE   144
#define W0_OFF   0
#define W1_OFF   4608
#define W2_OFF   13824
#define B0_OFF   14848
#define B1_OFF   15104
#define ACT_OFF  15360
#define SMEM_TOTAL 33792

__device__ __forceinline__ uint32_t smem_u32(const void* p) {
    uint32_t a;
    asm("{ .reg .u64 t; cvta.to.shared.u64 t, %1; cvt.u32.u64 %0, t; }"
        : "=r"(a) : "l"(p));
    return a;
}

#define LDM_X4(r0, r1, r2, r3, addr) \
    asm volatile("ldmatrix.sync.aligned.m8n8.x4.shared.b16 {%0,%1,%2,%3}, [%4];" \
        : "=r"(r0), "=r"(r1), "=r"(r2), "=r"(r3) : "r"(addr))

#define LDM_X4_T(r0, r1, r2, r3, addr) \
    asm volatile("ldmatrix.sync.aligned.m8n8.x4.trans.shared.b16 {%0,%1,%2,%3}, [%4];" \
        : "=r"(r0), "=r"(r1), "=r"(r2), "=r"(r3) : "r"(addr))

#define MMA16816(d, a0, a1, a2, a3, b0, b1) \
    asm volatile("mma.sync.aligned.m16n8k16.row.col.f32.f16.f16.f32 " \
        "{%0,%1,%2,%3}, {%4,%5,%6,%7}, {%8,%9}, {%0,%1,%2,%3};" \
        : "+f"((d)[0]), "+f"((d)[1]), "+f"((d)[2]), "+f"((d)[3]) \
        : "r"(a0), "r"(a1), "r"(a2), "r"(a3), "r"(b0), "r"(b1))

__global__ void __launch_bounds__(128)
fused_mlp_kernel(const float2* __restrict__ x,
                 const float*  __restrict__ w0, const float* __restrict__ b0,
                 const float*  __restrict__ w1, const float* __restrict__ b1,
                 const float*  __restrict__ w2, const float* __restrict__ b2,
                 float* __restrict__ out, int N)
{
    __shared__ __align__(16) uint8_t sm[SMEM_TOTAL];
    const uint32_t sbase = smem_u32(sm);

    const int tid  = threadIdx.x;
    const int wrp  = tid >> 5;
    const int lane = tid & 31;
    const int gi   = blockIdx.x * 128 + tid;

    // ---- Stage weights fp32->fp16 into smem (144B stride rows) ----
    for (int i = tid; i < 1024; i += 128) {            // w0: [32 K][64 N]
        const int k = i >> 5, n2 = i & 31;
        const float2 v = ((const float2*)w0)[i];
        *(__half2*)(sm + W0_OFF + k * STRIDE + n2 * 4) = __floats2half2_rn(v.x, v.y);
    }
    for (int i = tid; i < 2048; i += 128) {            // w1: [64 K][64 N]
        const int k = i >> 5, n2 = i & 31;
        const float2 v = ((const float2*)w1)[i];
        *(__half2*)(sm + W1_OFF + k * STRIDE + n2 * 4) = __floats2half2_rn(v.x, v.y);
    }
    if (tid < 64) {
        ((float4*)(sm + W2_OFF))[tid] =
            make_float4(w2[tid * 3 + 0], w2[tid * 3 + 1], w2[tid * 3 + 2], 0.0f);
        ((float*)(sm + B0_OFF))[tid] = b0[tid];
        ((float*)(sm + B1_OFF))[tid] = b1[tid];
    }

    // ---------------- Hash-grid encode (paired x-corner gathers) ----------------
    const float2 xi = (gi < N) ? x[gi] : make_float2(0.0f, 0.0f);
    float feat[32];
    #pragma unroll
    for (int l = 0; l < 16; l++) {
        const float s  = SCALES[l];
        const float px = xi.x * s, py = xi.y * s;
        const float fx = floorf(px), fy = floorf(py);
        const float tx = px - fx,  ty = py - fy;
        const unsigned ix0 = (unsigned)fx, iy0 = (unsigned)fy;
        const float* lvl = g_enc2 + (size_t)l * (HASHMAP_SIZE * 2);

        float accx = 0.0f, accy = 0.0f;
        #pragma unroll
        for (int cy = 0; cy < 2; cy++) {
            const unsigned t  = (iy0 + (unsigned)cy) * 2654435761u;
            const unsigned i0 = (ix0 ^ t) & HMASK;
            const unsigned i1 = ((ix0 + 1u) ^ t) & HMASK;
            const float wy  = cy ? ty : (1.0f - ty);
            const float wx0 = (1.0f - tx) * wy;
            const float wx1 = tx * wy;

            // 16B load covering the aligned pair {i0&~1, i0|1}
            const float4 v = __ldg((const float4*)(lvl + (size_t)(i0 & ~1u) * 2));
            const float e0x = (i0 & 1u) ? v.z : v.x;
            const float e0y = (i0 & 1u) ? v.w : v.y;
            float e1x, e1y;
            if (i1 == (i0 ^ 1u)) {          // ix even: corner 1 in same block
                e1x = (i0 & 1u) ? v.x : v.z;
                e1y = (i0 & 1u) ? v.y : v.w;
            } else {                        // ix odd: separate gather
                const float2 e = __ldg((const float2*)(lvl + (size_t)i1 * 2));
                e1x = e.x; e1y = e.y;
            }
            accx = fmaf(wx0, e0x, accx);
            accy = fmaf(wx0, e0y, accy);
            accx = fmaf(wx1, e1x, accx);
            accy = fmaf(wx1, e1y, accy);
        }
        feat[2 * l + 0] = accx;
        feat[2 * l + 1] = accy;
    }

    // Store feats (fp16) to this warp's act tile: row=lane, 64B of data
    const uint32_t actBase = sbase + ACT_OFF + wrp * 32 * STRIDE;
    {
        uint32_t fp[16];
        #pragma unroll
        for (int p = 0; p < 16; p++) {
            const __half2 h2 = __floats2half2_rn(feat[2 * p], feat[2 * p + 1]);
            fp[p] = *(const uint32_t*)&h2;
        }
        uint8_t* row = sm + ACT_OFF + (wrp * 32 + lane) * STRIDE;
        #pragma unroll
        for (int c = 0; c < 4; c++)
            *(uint4*)(row + c * 16) =
                make_uint4(fp[4 * c], fp[4 * c + 1], fp[4 * c + 2], fp[4 * c + 3]);
    }
    __syncthreads();   // weights + feats visible

    // Fragment address helpers
    const uint32_t aRow   = (uint32_t)(lane & 15);
    const uint32_t aColB  = (uint32_t)((lane >> 4) << 4);
    const int      bGrp   = lane >> 3;
    const uint32_t bRow   = (uint32_t)((lane & 7) + ((bGrp & 1) << 3));
    const uint32_t bColB  = (uint32_t)((bGrp >> 1) << 4);

    float acc[2][8][4];

    // ---------------- Layer 1: [32x32] @ [32x64] ----------------
    #pragma unroll
    for (int mt = 0; mt < 2; mt++)
        #pragma unroll
        for (int nt = 0; nt < 8; nt++)
            #pragma unroll
            for (int q = 0; q < 4; q++) acc[mt][nt][q] = 0.0f;

    #pragma unroll
    for (int kt = 0; kt < 2; kt++) {
        uint32_t a0[4], a1[4];
        LDM_X4(a0[0], a0[1], a0[2], a0[3],
               actBase + (0 * 16 + aRow) * STRIDE + aColB + kt * 32);
        LDM_X4(a1[0], a1[1], a1[2], a1[3],
               actBase + (1 * 16 + aRow) * STRIDE + aColB + kt * 32);
        #pragma unroll
        for (int ntp = 0; ntp < 4; ntp++) {
            uint32_t bf[4];
            LDM_X4_T(bf[0], bf[1], bf[2], bf[3],
                     sbase + W0_OFF + (kt * 16 + bRow) * STRIDE + ntp * 32 + bColB);
            MMA16816(acc[0][2 * ntp + 0], a0[0], a0[1], a0[2], a0[3], bf[0], bf[1]);
            MMA16816(acc[0][2 * ntp + 1], a0[0], a0[1], a0[2], a0[3], bf[2], bf[3]);
            MMA16816(acc[1][2 * ntp + 0], a1[0], a1[1], a1[2], a1[3], bf[0], bf[1]);
            MMA16816(acc[1][2 * ntp + 1], a1[0], a1[1], a1[2], a1[3], bf[2], bf[3]);
        }
    }

    // Epilogue 1: relu(acc + b0) -> fp16 -> act tile (overwrites feats)
    __syncwarp();
    {
        const float* bb0 = (const float*)(sm + B0_OFF);
        const int g = lane >> 2, cp = (lane & 3) * 2;
        #pragma unroll
        for (int mt = 0; mt < 2; mt++)
            #pragma unroll
            for (int nt = 0; nt < 8; nt++) {
                const int col = nt * 8 + cp;
                const float bA = bb0[col], bB = bb0[col + 1];
                const __half2 hA = __floats2half2_rn(
                    fmaxf(acc[mt][nt][0] + bA, 0.0f), fmaxf(acc[mt][nt][1] + bB, 0.0f));
                const __half2 hB = __floats2half2_rn(
                    fmaxf(acc[mt][nt][2] + bA, 0.0f), fmaxf(acc[mt][nt][3] + bB, 0.0f));
                uint8_t* base = sm + ACT_OFF + wrp * 32 * STRIDE;
                *(uint32_t*)(base + (mt * 16 + g)     * STRIDE + col * 2) = *(const uint32_t*)&hA;
                *(uint32_t*)(base + (mt * 16 + g + 8) * STRIDE + col * 2) = *(const uint32_t*)&hB;
            }
    }
    __syncwarp();

    // ---------------- Layer 2: [32x64] @ [64x64] ----------------
    #pragma unroll
    for (int mt = 0; mt < 2; mt++)
        #pragma unroll
        for (int nt = 0; nt < 8; nt++)
            #pragma unroll
            for (int q = 0; q < 4; q++) acc[mt][nt][q] = 0.0f;

    #pragma unroll
    for (int kt = 0; kt < 4; kt++) {
        uint32_t a0[4], a1[4];
        LDM_X4(a0[0], a0[1], a0[2], a0[3],
               actBase + (0 * 16 + aRow) * STRIDE + aColB + kt * 32);
        LDM_X4(a1[0], a1[1], a1[2], a1[3],
               actBase + (1 * 16 + aRow) * STRIDE + aColB + kt * 32);
        #pragma unroll
        for (int ntp = 0; ntp < 4; ntp++) {
            uint32_t bf[4];
            LDM_X4_T(bf[0], bf[1], bf[2], bf[3],
                     sbase + W1_OFF + (kt * 16 + bRow) * STRIDE + ntp * 32 + bColB);
            MMA16816(acc[0][2 * ntp + 0], a0[0], a0[1], a0[2], a0[3], bf[0], bf[1]);
            MMA16816(acc[0][2 * ntp + 1], a0[0], a0[1], a0[2], a0[3], bf[2], bf[3]);
            MMA16816(acc[1][2 * ntp + 0], a1[0], a1[1], a1[2], a1[3], bf[0], bf[1]);
            MMA16816(acc[1][2 * ntp + 1], a1[0], a1[1], a1[2], a1[3], bf[2], bf[3]);
        }
    }

    // Epilogue 2: relu(acc + b1), layer 3 fp32, 4-lane shuffle reduce, store
    {
        const float*  bb1 = (const float*)(sm + B1_OFF);
        const float4* ww2 = (const float4*)(sm + W2_OFF);
        const int g = lane >> 2, cp = (lane & 3) * 2;
        #pragma unroll
        for (int mt = 0; mt < 2; mt++) {
            float oA0 = 0.0f, oA1 = 0.0f, oA2 = 0.0f;
            float oB0 = 0.0f, oB1 = 0.0f, oB2 = 0.0f;
            #pragma unroll
            for (int nt = 0; nt < 8; nt++) {
                const int col = nt * 8 + cp;
                const float4 wA = ww2[col];
                const float4 wB = ww2[col + 1];
                const float bA = bb1[col], bB = bb1[col + 1];
                const float vA0 = fmaxf(acc[mt][nt][0] + bA, 0.0f);
                const float vA1 = fmaxf(acc[mt][nt][1] + bB, 0.0f);
                const float vB0 = fmaxf(acc[mt][nt][2] + bA, 0.0f);
                const float vB1 = fmaxf(acc[mt][nt][3] + bB, 0.0f);
                oA0 = fmaf(vA0, wA.x, fmaf(vA1, wB.x, oA0));
                oA1 = fmaf(vA0, wA.y, fmaf(vA1, wB.y, oA1));
                oA2 = fmaf(vA0, wA.z, fmaf(vA1, wB.z, oA2));
                oB0 = fmaf(vB0, wA.x, fmaf(vB1, wB.x, oB0));
                oB1 = fmaf(vB0, wA.y, fmaf(vB1, wB.y, oB1));
                oB2 = fmaf(vB0, wA.z, fmaf(vB1, wB.z, oB2));
            }
            #pragma unroll
            for (int d = 1; d < 4; d <<= 1) {
                oA0 += __shfl_xor_sync(0xffffffffu, oA0, d);
                oA1 += __shfl_xor_sync(0xffffffffu, oA1, d);
                oA2 += __shfl_xor_sync(0xffffffffu, oA2, d);
                oB0 += __shfl_xor_sync(0xffffffffu, oB0, d);
                oB1 += __shfl_xor_sync(0xffffffffu, oB1, d);
                oB2 += __shfl_xor_sync(0xffffffffu, oB2, d);
            }
            if ((lane & 3) == 0) {
                const float c0 = __ldg(b2 + 0), c1 = __ldg(b2 + 1), c2 = __ldg(b2 + 2);
                const int pA = blockIdx.x * 128 + wrp * 32 + mt * 16 + g;
                const int pB = pA + 8;
                if (pA < N) {
                    out[pA * 3 + 0] = oA0 + c0;
                    out[pA * 3 + 1] = oA1 + c1;
                    out[pA * 3 + 2] = oA2 + c2;
                }
                if (pB < N) {
                    out[pB * 3 + 0] = oB0 + c0;
                    out[pB * 3 + 1] = oB1 + c1;
                    out[pB * 3 + 2] = oB2 + c2;
                }
            }
        }
    }
}

extern "C" void kernel_launch(void* const* d_in, const int* in_sizes, int n_in,
                              void* d_out, int out_size)
{
    const float2* x   = (const float2*)d_in[0];
    const float*  enc = (const float*) d_in[1];
    const float*  w0  = (const float*) d_in[2];
    const float*  b0  = (const float*) d_in[3];
    const float*  w1  = (const float*) d_in[4];
    const float*  b1  = (const float*) d_in[5];
    const float*  w2  = (const float*) d_in[6];
    const float*  b2  = (const float*) d_in[7];
    float* out = (float*)d_out;

    const int N = in_sizes[0] / 2;
    relayout_kernel<<<(16 * HASHMAP_SIZE) / 256, 256>>>(enc);
    const int blocks = (N + 127) / 128;
    fused_mlp_kernel<<<blocks, 128>>>(x, w0, b0, w1, b1, w2, b2, out, N);
}